// round 2
// baseline (speedup 1.0000x reference)
#include <cuda_runtime.h>
#include <cstdint>

// Problem constants
constexpr int Bb   = 64;
constexpr int IC   = 32;
constexpr int PC   = 128;
constexpr int RC   = 32;
constexpr int OC   = 128;
constexpr int Hh   = 96;
constexpr int Ww   = 320;
constexpr int Npts = 2048;
constexpr float EPS = 1e-5f;

constexpr int TILE    = 64;                 // points per block
constexpr int THREADS = 256;
constexpr int TILES_PER_B = Npts / TILE;    // 32
constexpr int GRID = Bb * TILES_PER_B;      // 2048

// Shared memory layout (floats)
constexpr int OFF_CAT = 0;                        // [256][64]
constexpr int OFF_IMG = OFF_CAT + 2 * PC * TILE;  // [32][64]
constexpr int OFF_SC1 = OFF_IMG + IC * TILE;
constexpr int OFF_SH1 = OFF_SC1 + PC;
constexpr int OFF_SC2 = OFF_SH1 + PC;
constexpr int OFF_SH2 = OFF_SC2 + OC;
constexpr int OFF_ATT = OFF_SH2 + OC;             // 64
constexpr int OFF_GX  = OFF_ATT + TILE;           // 64
constexpr int OFF_GY  = OFF_GX + TILE;            // 64
constexpr int SMEM_FLOATS = OFF_GY + TILE;
constexpr int SMEM_BYTES  = SMEM_FLOATS * 4;      // 76,544 B -> 2 blocks/SM

// Prepped (transposed / folded) parameters in device scratch
__device__ __align__(16) float d_WfuseT[2 * PC * OC];  // [k=256][oc=128]
__device__ __align__(16) float d_WiaT[IC * PC];        // [k=32][oc=128]
__device__ __align__(16) float d_Wf1T[IC * RC];        // [k=32][r=32]
__device__ __align__(16) float d_Wf2T[PC * RC];        // [k=128][r=32]
__device__ __align__(16) float d_sc1[PC], d_sh1[PC], d_sc2[OC], d_sh2[OC];
__device__ __align__(16) float d_br[RC], d_w3[RC];
__device__ float d_b3[1];

#define DEV __device__ __forceinline__
typedef unsigned long long u64;

// ---- packed f32x2 helpers (Blackwell FFMA2; ptxas never emits from C++) ----
DEV u64 pk2(float v) {
    u64 r;
    asm("mov.b64 %0, {%1, %1};" : "=l"(r) : "f"(v));
    return r;
}
DEV u64 f2fma(u64 a, u64 b, u64 c) {
    u64 d;
    asm("fma.rn.f32x2 %0, %1, %2, %3;" : "=l"(d) : "l"(a), "l"(b), "l"(c));
    return d;
}
DEV float2 upk(u64 a) {
    float2 f;
    asm("mov.b64 {%0, %1}, %2;" : "=f"(f.x), "=f"(f.y) : "l"(a));
    return f;
}
DEV float tanh_ap(float x) {
    float y;
    asm("tanh.approx.f32 %0, %1;" : "=f"(y) : "f"(x));
    return y;
}

// ---------------- prep: transposes + BN folding ----------------
__global__ void prep_kernel(const float* __restrict__ W_ia, const float* __restrict__ b_ia,
                            const float* __restrict__ g1, const float* __restrict__ bt1,
                            const float* __restrict__ m1, const float* __restrict__ v1,
                            const float* __restrict__ Wf1, const float* __restrict__ bf1,
                            const float* __restrict__ Wf2, const float* __restrict__ bf2,
                            const float* __restrict__ Wf3, const float* __restrict__ bf3,
                            const float* __restrict__ W_fuse, const float* __restrict__ b_fuse,
                            const float* __restrict__ g2, const float* __restrict__ bt2,
                            const float* __restrict__ m2, const float* __restrict__ v2)
{
    int i = blockIdx.x * blockDim.x + threadIdx.x;
    if (i < 2 * PC * OC) { int k = i / OC, oc = i % OC; d_WfuseT[i] = W_fuse[oc * (2 * PC) + k]; }
    if (i < IC * PC)     { int k = i / PC, oc = i % PC; d_WiaT[i]   = W_ia[oc * IC + k]; }
    if (i < PC * RC)     { int k = i / RC, r  = i % RC; d_Wf2T[i]   = Wf2[r * PC + k]; }
    if (i < IC * RC)     { int k = i / RC, r  = i % RC; d_Wf1T[i]   = Wf1[r * IC + k]; }
    if (i < PC) {
        float s1 = g1[i] * rsqrtf(v1[i] + EPS);
        d_sc1[i] = s1;
        d_sh1[i] = (b_ia[i] - m1[i]) * s1 + bt1[i];
        float s2 = g2[i] * rsqrtf(v2[i] + EPS);
        d_sc2[i] = s2;
        d_sh2[i] = (b_fuse[i] - m2[i]) * s2 + bt2[i];
    }
    if (i < RC) { d_br[i] = bf1[i] + bf2[i]; d_w3[i] = Wf3[i]; }
    if (i == 0) d_b3[0] = bf3[0];
}

extern __shared__ float sm[];

__global__ void __launch_bounds__(THREADS, 2)
fused_rcnn_kernel(const float* __restrict__ img_map,   // (B,IC,H,W)
                  const float* __restrict__ xy,        // (B,N,2)
                  const float* __restrict__ pf,        // (B,PC,N)
                  float* __restrict__ out)             // (B,OC,N)
{
    const int tid = threadIdx.x;
    const int blk = blockIdx.x;
    const int b   = blk / TILES_PER_B;
    const int n0  = (blk % TILES_PER_B) * TILE;

    float* s_cat = sm + OFF_CAT;
    float* s_img = sm + OFF_IMG;
    float* s_sc1 = sm + OFF_SC1;
    float* s_sh1 = sm + OFF_SH1;
    float* s_sc2 = sm + OFF_SC2;
    float* s_sh2 = sm + OFF_SH2;
    float* s_att = sm + OFF_ATT;
    float* s_gx  = sm + OFF_GX;
    float* s_gy  = sm + OFF_GY;

    const int wid  = tid >> 5;
    const int lane = tid & 31;

    // ---------------- Phase 0: cooperative loads ----------------
    // point_feas tile -> cat rows [0,128): 128 rows x 64 cols, as float4
    #pragma unroll
    for (int it = 0; it < 8; it++) {
        int i = tid + it * THREADS;              // 0..2047
        int c = i >> 4, q = i & 15;
        float4 v = __ldg((const float4*)(pf + (size_t)(b * PC + c) * Npts + n0) + q);
        *(float4*)(s_cat + c * TILE + q * 4) = v;
    }
    if (tid < PC) {
        s_sc1[tid] = d_sc1[tid]; s_sh1[tid] = d_sh1[tid];
        s_sc2[tid] = d_sc2[tid]; s_sh2[tid] = d_sh2[tid];
    }
    if (tid < TILE) {
        float2 p = __ldg((const float2*)xy + (size_t)b * Npts + n0 + tid);
        s_gx[tid] = ((p.x + 1.0f) * (float)Ww - 1.0f) * 0.5f;
        s_gy[tid] = ((p.y + 1.0f) * (float)Hh - 1.0f) * 0.5f;
    }
    __syncthreads();

    // ---------------- Phase 1: bilinear gather (IC x TILE) ----------------
    {
        int pt = tid & 63, cg = tid >> 6;        // cg: 0..3, 8 channels each
        float ix = s_gx[pt], iy = s_gy[pt];
        float fx0 = floorf(ix), fy0 = floorf(iy);
        int x0 = (int)fx0, y0 = (int)fy0;
        float wx1 = ix - fx0, wy1 = iy - fy0;
        float wx0 = 1.0f - wx1, wy0 = 1.0f - wy1;
        bool x0v = (x0 >= 0) && (x0 < Ww);
        bool x1v = (x0 + 1 >= 0) && (x0 + 1 < Ww);
        bool y0v = (y0 >= 0) && (y0 < Hh);
        bool y1v = (y0 + 1 >= 0) && (y0 + 1 < Hh);
        float w00 = (x0v && y0v) ? wx0 * wy0 : 0.0f;
        float w01 = (x1v && y0v) ? wx1 * wy0 : 0.0f;
        float w10 = (x0v && y1v) ? wx0 * wy1 : 0.0f;
        float w11 = (x1v && y1v) ? wx1 * wy1 : 0.0f;
        int xc0 = min(max(x0, 0), Ww - 1), xc1 = min(max(x0 + 1, 0), Ww - 1);
        int yc0 = min(max(y0, 0), Hh - 1), yc1 = min(max(y0 + 1, 0), Hh - 1);
        size_t o00 = (size_t)yc0 * Ww + xc0, o01 = (size_t)yc0 * Ww + xc1;
        size_t o10 = (size_t)yc1 * Ww + xc0, o11 = (size_t)yc1 * Ww + xc1;
        const float* base = img_map + ((size_t)b * IC + cg * 8) * (Hh * Ww);
        #pragma unroll
        for (int c = 0; c < 8; c++) {
            const float* p = base + (size_t)c * (Hh * Ww);
            float v = w00 * __ldg(p + o00) + w01 * __ldg(p + o01)
                    + w10 * __ldg(p + o10) + w11 * __ldg(p + o11);
            s_img[(cg * 8 + c) * TILE + pt] = v;
        }
    }
    __syncthreads();

    // ---------------- Phase 2+3: attention (lane = r, 8 pts per warp) ----------------
    {
        const int p0 = wid * 8;
        u64 a0 = 0, a1 = 0, a2 = 0, a3 = 0;
        const float br  = d_br[lane];
        const float w3v = d_w3[lane];
        #pragma unroll 4
        for (int k = 0; k < IC; k++) {
            u64 w = pk2(d_Wf1T[k * RC + lane]);             // coalesced LDG
            ulonglong2 c0 = *(const ulonglong2*)(s_img + k * TILE + p0);      // broadcast
            ulonglong2 c1 = *(const ulonglong2*)(s_img + k * TILE + p0 + 4);
            a0 = f2fma(w, c0.x, a0); a1 = f2fma(w, c0.y, a1);
            a2 = f2fma(w, c1.x, a2); a3 = f2fma(w, c1.y, a3);
        }
        #pragma unroll 4
        for (int k = 0; k < PC; k++) {
            u64 w = pk2(d_Wf2T[k * RC + lane]);
            ulonglong2 c0 = *(const ulonglong2*)(s_cat + k * TILE + p0);
            ulonglong2 c1 = *(const ulonglong2*)(s_cat + k * TILE + p0 + 4);
            a0 = f2fma(w, c0.x, a0); a1 = f2fma(w, c0.y, a1);
            a2 = f2fma(w, c1.x, a2); a3 = f2fma(w, c1.y, a3);
        }
        float v[8];
        float2 t;
        t = upk(a0); v[0] = t.x; v[1] = t.y;
        t = upk(a1); v[2] = t.x; v[3] = t.y;
        t = upk(a2); v[4] = t.x; v[5] = t.y;
        t = upk(a3); v[6] = t.x; v[7] = t.y;
        #pragma unroll
        for (int j = 0; j < 8; j++) v[j] = tanh_ap(v[j] + br) * w3v;
        #pragma unroll
        for (int off = 16; off > 0; off >>= 1) {
            #pragma unroll
            for (int j = 0; j < 8; j++)
                v[j] += __shfl_xor_sync(0xffffffffu, v[j], off);
        }
        if (lane == 0) {
            float b3 = d_b3[0];
            #pragma unroll
            for (int j = 0; j < 8; j++)
                s_att[p0 + j] = 1.0f / (1.0f + __expf(-(v[j] + b3)));
        }
    }
    __syncthreads();

    const int g  = wid & 3;          // oc group (32 oc)
    const int h  = wid >> 2;         // pt half
    const int pt = h * 32 + lane;    // this lane's point

    // ---------------- Phase 4: img_new = relu(bn1(W_ia @ img)) * att ----------------
    {
        u64 A[16];
        #pragma unroll
        for (int i = 0; i < 16; i++) A[i] = 0;
        #pragma unroll 4
        for (int k = 0; k < IC; k++) {
            u64 cs = pk2(s_img[k * TILE + pt]);                         // coalesced LDS
            const ulonglong2* wp = (const ulonglong2*)(d_WiaT + k * PC + g * 32);
            #pragma unroll
            for (int j = 0; j < 8; j++) {
                ulonglong2 w = wp[j];                                   // broadcast LDG
                A[2 * j]     = f2fma(w.x, cs, A[2 * j]);
                A[2 * j + 1] = f2fma(w.y, cs, A[2 * j + 1]);
            }
        }
        float att = s_att[pt];
        #pragma unroll
        for (int q = 0; q < 8; q++) {
            int oc = g * 32 + q * 4;
            float4 sc = *(const float4*)(s_sc1 + oc);
            float4 sh = *(const float4*)(s_sh1 + oc);
            float2 p0v = upk(A[2 * q]);
            float2 p1v = upk(A[2 * q + 1]);
            s_cat[(PC + oc + 0) * TILE + pt] = fmaxf(p0v.x * sc.x + sh.x, 0.0f) * att;
            s_cat[(PC + oc + 1) * TILE + pt] = fmaxf(p0v.y * sc.y + sh.y, 0.0f) * att;
            s_cat[(PC + oc + 2) * TILE + pt] = fmaxf(p1v.x * sc.z + sh.z, 0.0f) * att;
            s_cat[(PC + oc + 3) * TILE + pt] = fmaxf(p1v.y * sc.w + sh.w, 0.0f) * att;
        }
    }
    __syncthreads();

    // ---------------- Phase 5: fuse GEMM (128 oc x 64 pt x 256 k) + bn2 + relu ----------------
    {
        u64 A[16];
        #pragma unroll
        for (int i = 0; i < 16; i++) A[i] = 0;
        #pragma unroll 2
        for (int k = 0; k < 2 * PC; k++) {
            u64 cs = pk2(s_cat[k * TILE + pt]);                         // 1 coalesced LDS wf
            const ulonglong2* wp = (const ulonglong2*)(d_WfuseT + k * OC + g * 32);
            #pragma unroll
            for (int j = 0; j < 8; j++) {
                ulonglong2 w = wp[j];                                   // broadcast LDG (L1)
                A[2 * j]     = f2fma(w.x, cs, A[2 * j]);
                A[2 * j + 1] = f2fma(w.y, cs, A[2 * j + 1]);
            }
        }
        float* op = out + ((size_t)b * OC) * Npts + n0 + pt;
        #pragma unroll
        for (int q = 0; q < 8; q++) {
            int oc = g * 32 + q * 4;
            float4 sc = *(const float4*)(s_sc2 + oc);
            float4 sh = *(const float4*)(s_sh2 + oc);
            float2 p0v = upk(A[2 * q]);
            float2 p1v = upk(A[2 * q + 1]);
            op[(size_t)(oc + 0) * Npts] = fmaxf(p0v.x * sc.x + sh.x, 0.0f);
            op[(size_t)(oc + 1) * Npts] = fmaxf(p0v.y * sc.y + sh.y, 0.0f);
            op[(size_t)(oc + 2) * Npts] = fmaxf(p1v.x * sc.z + sh.z, 0.0f);
            op[(size_t)(oc + 3) * Npts] = fmaxf(p1v.y * sc.w + sh.w, 0.0f);
        }
    }
}

extern "C" void kernel_launch(void* const* d_in, const int* in_sizes, int n_in,
                              void* d_out, int out_size) {
    (void)in_sizes; (void)n_in; (void)out_size;
    const float* img_map = (const float*)d_in[0];
    const float* xy      = (const float*)d_in[1];
    const float* pf      = (const float*)d_in[2];
    const float* W_ia    = (const float*)d_in[3];
    const float* b_ia    = (const float*)d_in[4];
    const float* g1      = (const float*)d_in[5];
    const float* bt1     = (const float*)d_in[6];
    const float* m1      = (const float*)d_in[7];
    const float* v1      = (const float*)d_in[8];
    const float* Wf1     = (const float*)d_in[9];
    const float* bf1     = (const float*)d_in[10];
    const float* Wf2     = (const float*)d_in[11];
    const float* bf2     = (const float*)d_in[12];
    const float* Wf3     = (const float*)d_in[13];
    const float* bf3     = (const float*)d_in[14];
    const float* W_fuse  = (const float*)d_in[15];
    const float* b_fuse  = (const float*)d_in[16];
    const float* g2      = (const float*)d_in[17];
    const float* bt2     = (const float*)d_in[18];
    const float* m2      = (const float*)d_in[19];
    const float* v2      = (const float*)d_in[20];
    float* out = (float*)d_out;

    prep_kernel<<<(2 * PC * OC + 255) / 256, 256>>>(
        W_ia, b_ia, g1, bt1, m1, v1, Wf1, bf1, Wf2, bf2, Wf3, bf3,
        W_fuse, b_fuse, g2, bt2, m2, v2);

    cudaFuncSetAttribute(fused_rcnn_kernel,
                         cudaFuncAttributeMaxDynamicSharedMemorySize, SMEM_BYTES);
    fused_rcnn_kernel<<<GRID, THREADS, SMEM_BYTES>>>(img_map, xy, pf, out);
}

// round 4
// speedup vs baseline: 1.9996x; 1.9996x over previous
#include <cuda_runtime.h>
#include <cstdint>

// Problem constants
constexpr int Bb   = 64;
constexpr int IC   = 32;
constexpr int PC   = 128;
constexpr int RC   = 32;
constexpr int OC   = 128;
constexpr int Hh   = 96;
constexpr int Ww   = 320;
constexpr int Npts = 2048;
constexpr float EPS = 1e-5f;

constexpr int TILE    = 64;                 // points per block
constexpr int THREADS = 256;
constexpr int TILES_PER_B = Npts / TILE;    // 32
constexpr int GRID = Bb * TILES_PER_B;      // 2048

// Shared memory layout (floats)
constexpr int OFF_CAT = 0;                        // [256][64]
constexpr int OFF_IMG = OFF_CAT + 2 * PC * TILE;  // [32][64]
constexpr int OFF_SC1 = OFF_IMG + IC * TILE;      // 128
constexpr int OFF_SH1 = OFF_SC1 + PC;             // 128
constexpr int OFF_SC2 = OFF_SH1 + PC;             // 128
constexpr int OFF_SH2 = OFF_SC2 + OC;             // 128
constexpr int OFF_ATT = OFF_SH2 + OC;             // 64
constexpr int OFF_ATP = OFF_ATT + TILE;           // 8*65 partials (padded stride)
constexpr int OFF_GX  = OFF_ATP + 8 * 65;         // 64
constexpr int OFF_GY  = OFF_GX + TILE;            // 64
constexpr int SMEM_FLOATS = OFF_GY + TILE;
constexpr int SMEM_BYTES  = SMEM_FLOATS * 4;      // ~78.7 KB -> 2 blocks/SM

// Prepped (transposed / folded) parameters in device scratch
__device__ __align__(16) float d_WfuseT[2 * PC * OC];  // [k=256][oc=128]
__device__ __align__(16) float d_WiaT[IC * PC];        // [k=32][oc=128]
__device__ __align__(16) float d_sc1[PC], d_sh1[PC], d_sc2[OC], d_sh2[OC];
__device__ __align__(16) float d_br[RC], d_w3[RC];
__device__ float d_b3[1];

#define DEV __device__ __forceinline__
typedef unsigned long long u64;

// ---- packed f32x2 helpers (Blackwell FFMA2) ----
DEV u64 pk2(float v) {
    u64 r;
    asm("mov.b64 %0, {%1, %1};" : "=l"(r) : "f"(v));
    return r;
}
DEV u64 f2fma(u64 a, u64 b, u64 c) {
    u64 d;
    asm("fma.rn.f32x2 %0, %1, %2, %3;" : "=l"(d) : "l"(a), "l"(b), "l"(c));
    return d;
}
DEV float2 upk(u64 a) {
    float2 f;
    asm("mov.b64 {%0, %1}, %2;" : "=f"(f.x), "=f"(f.y) : "l"(a));
    return f;
}
DEV float tanh_ap(float x) {
    float y;
    asm("tanh.approx.f32 %0, %1;" : "=f"(y) : "f"(x));
    return y;
}

// ---------------- prep: transposes + BN folding ----------------
__global__ void prep_kernel(const float* __restrict__ W_ia, const float* __restrict__ b_ia,
                            const float* __restrict__ g1, const float* __restrict__ bt1,
                            const float* __restrict__ m1, const float* __restrict__ v1,
                            const float* __restrict__ bf1, const float* __restrict__ bf2,
                            const float* __restrict__ Wf3, const float* __restrict__ bf3,
                            const float* __restrict__ W_fuse, const float* __restrict__ b_fuse,
                            const float* __restrict__ g2, const float* __restrict__ bt2,
                            const float* __restrict__ m2, const float* __restrict__ v2)
{
    int i = blockIdx.x * blockDim.x + threadIdx.x;
    if (i < 2 * PC * OC) { int k = i / OC, oc = i % OC; d_WfuseT[i] = W_fuse[oc * (2 * PC) + k]; }
    if (i < IC * PC)     { int k = i / PC, oc = i % PC; d_WiaT[i]   = W_ia[oc * IC + k]; }
    if (i < PC) {
        float s1 = g1[i] * rsqrtf(v1[i] + EPS);
        d_sc1[i] = s1;
        d_sh1[i] = (b_ia[i] - m1[i]) * s1 + bt1[i];
        float s2 = g2[i] * rsqrtf(v2[i] + EPS);
        d_sc2[i] = s2;
        d_sh2[i] = (b_fuse[i] - m2[i]) * s2 + bt2[i];
    }
    if (i < RC) { d_br[i] = bf1[i] + bf2[i]; d_w3[i] = Wf3[i]; }
    if (i == 0) d_b3[0] = bf3[0];
}

extern __shared__ float sm[];

__global__ void __launch_bounds__(THREADS, 2)
fused_rcnn_kernel(const float* __restrict__ img_map,   // (B,IC,H,W)
                  const float* __restrict__ xy,        // (B,N,2)
                  const float* __restrict__ pf,        // (B,PC,N)
                  const float* __restrict__ Wf1,       // (RC,IC)  [r][k]
                  const float* __restrict__ Wf2,       // (RC,PC)  [r][k]
                  float* __restrict__ out)             // (B,OC,N)
{
    const int tid = threadIdx.x;
    const int blk = blockIdx.x;
    const int b   = blk / TILES_PER_B;
    const int n0  = (blk % TILES_PER_B) * TILE;

    float* s_cat = sm + OFF_CAT;
    float* s_img = sm + OFF_IMG;
    float* s_sc1 = sm + OFF_SC1;
    float* s_sh1 = sm + OFF_SH1;
    float* s_sc2 = sm + OFF_SC2;
    float* s_sh2 = sm + OFF_SH2;
    float* s_att = sm + OFF_ATT;
    float* s_atp = sm + OFF_ATP;
    float* s_gx  = sm + OFF_GX;
    float* s_gy  = sm + OFF_GY;

    const int wid  = tid >> 5;
    const int lane = tid & 31;
    const int og   = lane & 3;     // oc sub-group / r sub-group
    const int pg   = lane >> 2;    // point group (8 pts each)
    const int p8   = pg * 8;

    // ---------------- Phase 0: cooperative loads ----------------
    #pragma unroll
    for (int it = 0; it < 8; it++) {
        int i = tid + it * THREADS;              // 0..2047
        int c = i >> 4, q = i & 15;
        float4 v = __ldg((const float4*)(pf + (size_t)(b * PC + c) * Npts + n0) + q);
        *(float4*)(s_cat + c * TILE + q * 4) = v;
    }
    if (tid < PC) {
        s_sc1[tid] = d_sc1[tid]; s_sh1[tid] = d_sh1[tid];
        s_sc2[tid] = d_sc2[tid]; s_sh2[tid] = d_sh2[tid];
    }
    if (tid < TILE) {
        float2 p = __ldg((const float2*)xy + (size_t)b * Npts + n0 + tid);
        s_gx[tid] = ((p.x + 1.0f) * (float)Ww - 1.0f) * 0.5f;
        s_gy[tid] = ((p.y + 1.0f) * (float)Hh - 1.0f) * 0.5f;
    }
    __syncthreads();

    // ---------------- Phase 1: bilinear gather (IC x TILE) ----------------
    {
        int pt = tid & 63, cg = tid >> 6;        // cg: 0..3, 8 channels each
        float ix = s_gx[pt], iy = s_gy[pt];
        float fx0 = floorf(ix), fy0 = floorf(iy);
        int x0 = (int)fx0, y0 = (int)fy0;
        float wx1 = ix - fx0, wy1 = iy - fy0;
        float wx0 = 1.0f - wx1, wy0 = 1.0f - wy1;
        bool x0v = (x0 >= 0) && (x0 < Ww);
        bool x1v = (x0 + 1 >= 0) && (x0 + 1 < Ww);
        bool y0v = (y0 >= 0) && (y0 < Hh);
        bool y1v = (y0 + 1 >= 0) && (y0 + 1 < Hh);
        float w00 = (x0v && y0v) ? wx0 * wy0 : 0.0f;
        float w01 = (x1v && y0v) ? wx1 * wy0 : 0.0f;
        float w10 = (x0v && y1v) ? wx0 * wy1 : 0.0f;
        float w11 = (x1v && y1v) ? wx1 * wy1 : 0.0f;
        int xc0 = min(max(x0, 0), Ww - 1), xc1 = min(max(x0 + 1, 0), Ww - 1);
        int yc0 = min(max(y0, 0), Hh - 1), yc1 = min(max(y0 + 1, 0), Hh - 1);
        size_t o00 = (size_t)yc0 * Ww + xc0, o01 = (size_t)yc0 * Ww + xc1;
        size_t o10 = (size_t)yc1 * Ww + xc0, o11 = (size_t)yc1 * Ww + xc1;
        const float* base = img_map + ((size_t)b * IC + cg * 8) * (Hh * Ww);
        #pragma unroll
        for (int c = 0; c < 8; c++) {
            const float* p = base + (size_t)c * (Hh * Ww);
            float v = w00 * __ldg(p + o00) + w01 * __ldg(p + o01)
                    + w10 * __ldg(p + o10) + w11 * __ldg(p + o11);
            s_img[(cg * 8 + c) * TILE + pt] = v;
        }
    }
    __syncthreads();

    // ---------------- Phase 2: attention GEMM (lane = 1 r x 8 pts) ----------------
    {
        const int r = wid * 4 + og;              // 0..31
        u64 a0 = 0, a1 = 0, a2 = 0, a3 = 0;
        // img part: k = 0..31, weights Wf1[r][k]
        #pragma unroll
        for (int k4 = 0; k4 < IC / 4; k4++) {
            float4 wv = __ldg((const float4*)(Wf1 + r * IC + k4 * 4));
            #pragma unroll
            for (int kk = 0; kk < 4; kk++) {
                const float* row = s_img + (k4 * 4 + kk) * TILE + p8;
                ulonglong2 c01 = *(const ulonglong2*)(row);
                ulonglong2 c23 = *(const ulonglong2*)(row + 4);
                u64 w = pk2(kk == 0 ? wv.x : kk == 1 ? wv.y : kk == 2 ? wv.z : wv.w);
                a0 = f2fma(w, c01.x, a0); a1 = f2fma(w, c01.y, a1);
                a2 = f2fma(w, c23.x, a2); a3 = f2fma(w, c23.y, a3);
            }
        }
        // pf part: k = 0..127, weights Wf2[r][k]
        #pragma unroll 4
        for (int k4 = 0; k4 < PC / 4; k4++) {
            float4 wv = __ldg((const float4*)(Wf2 + r * PC + k4 * 4));
            #pragma unroll
            for (int kk = 0; kk < 4; kk++) {
                const float* row = s_cat + (k4 * 4 + kk) * TILE + p8;
                ulonglong2 c01 = *(const ulonglong2*)(row);
                ulonglong2 c23 = *(const ulonglong2*)(row + 4);
                u64 w = pk2(kk == 0 ? wv.x : kk == 1 ? wv.y : kk == 2 ? wv.z : wv.w);
                a0 = f2fma(w, c01.x, a0); a1 = f2fma(w, c01.y, a1);
                a2 = f2fma(w, c23.x, a2); a3 = f2fma(w, c23.y, a3);
            }
        }
        float br  = __ldg(d_br + r);
        float w3v = __ldg(d_w3 + r);
        float v[8];
        float2 t;
        t = upk(a0); v[0] = t.x; v[1] = t.y;
        t = upk(a1); v[2] = t.x; v[3] = t.y;
        t = upk(a2); v[4] = t.x; v[5] = t.y;
        t = upk(a3); v[6] = t.x; v[7] = t.y;
        #pragma unroll
        for (int j = 0; j < 8; j++) v[j] = tanh_ap(v[j] + br) * w3v;
        // reduce over og (4 r's of this warp): lanes og, og^1, og^2
        #pragma unroll
        for (int j = 0; j < 8; j++) {
            v[j] += __shfl_xor_sync(0xffffffffu, v[j], 1);
            v[j] += __shfl_xor_sync(0xffffffffu, v[j], 2);
        }
        if (og == 0) {
            #pragma unroll
            for (int j = 0; j < 8; j++) s_atp[wid * 65 + p8 + j] = v[j];
        }
    }
    __syncthreads();
    if (tid < TILE) {
        float s = d_b3[0];
        #pragma unroll
        for (int w = 0; w < 8; w++) s += s_atp[w * 65 + tid];
        s_att[tid] = 1.0f / (1.0f + __expf(-s));
    }
    __syncthreads();

    const int oc0 = wid * 16 + og * 4;           // this lane's 4 output channels

    // ---------------- Phase 4: img_new = relu(bn1(W_ia @ img)) * att ----------------
    {
        u64 A[8];
        #pragma unroll
        for (int i = 0; i < 8; i++) A[i] = 0;
        u64 B4[8];
        #pragma unroll
        for (int i = 0; i < 8; i++) B4[i] = 0;
        #pragma unroll 4
        for (int k = 0; k < IC; k++) {
            float4 wv = __ldg((const float4*)(d_WiaT + k * PC + oc0));
            const float* row = s_img + k * TILE + p8;
            ulonglong2 c01 = *(const ulonglong2*)(row);
            ulonglong2 c23 = *(const ulonglong2*)(row + 4);
            u64 w0 = pk2(wv.x), w1 = pk2(wv.y), w2 = pk2(wv.z), w3 = pk2(wv.w);
            A[0] = f2fma(w0, c01.x, A[0]); A[1] = f2fma(w0, c01.y, A[1]);
            A[2] = f2fma(w1, c01.x, A[2]); A[3] = f2fma(w1, c01.y, A[3]);
            A[4] = f2fma(w2, c01.x, A[4]); A[5] = f2fma(w2, c01.y, A[5]);
            A[6] = f2fma(w3, c01.x, A[6]); A[7] = f2fma(w3, c01.y, A[7]);
            B4[0] = f2fma(w0, c23.x, B4[0]); B4[1] = f2fma(w0, c23.y, B4[1]);
            B4[2] = f2fma(w1, c23.x, B4[2]); B4[3] = f2fma(w1, c23.y, B4[3]);
            B4[4] = f2fma(w2, c23.x, B4[4]); B4[5] = f2fma(w2, c23.y, B4[5]);
            B4[6] = f2fma(w3, c23.x, B4[6]); B4[7] = f2fma(w3, c23.y, B4[7]);
        }
        float4 at0 = *(const float4*)(s_att + p8);
        float4 at1 = *(const float4*)(s_att + p8 + 4);
        #pragma unroll
        for (int i = 0; i < 4; i++) {
            int oc = oc0 + i;
            float sc = s_sc1[oc], sh = s_sh1[oc];
            float2 q0 = upk(A[2 * i]), q1 = upk(A[2 * i + 1]);
            float2 q2 = upk(B4[2 * i]), q3 = upk(B4[2 * i + 1]);
            float4 o0, o1;
            o0.x = fmaxf(q0.x * sc + sh, 0.f) * at0.x;
            o0.y = fmaxf(q0.y * sc + sh, 0.f) * at0.y;
            o0.z = fmaxf(q1.x * sc + sh, 0.f) * at0.z;
            o0.w = fmaxf(q1.y * sc + sh, 0.f) * at0.w;
            o1.x = fmaxf(q2.x * sc + sh, 0.f) * at1.x;
            o1.y = fmaxf(q2.y * sc + sh, 0.f) * at1.y;
            o1.z = fmaxf(q3.x * sc + sh, 0.f) * at1.z;
            o1.w = fmaxf(q3.y * sc + sh, 0.f) * at1.w;
            float* dst = s_cat + (PC + oc) * TILE + p8;
            *(float4*)(dst)     = o0;
            *(float4*)(dst + 4) = o1;
        }
    }
    __syncthreads();

    // ---------------- Phase 5: fuse GEMM (4 oc x 8 pts per lane, k=256) ----------------
    {
        u64 A[8], B4[8];
        #pragma unroll
        for (int i = 0; i < 8; i++) { A[i] = 0; B4[i] = 0; }
        #pragma unroll 4
        for (int k = 0; k < 2 * PC; k++) {
            float4 wv = __ldg((const float4*)(d_WfuseT + k * OC + oc0));
            const float* row = s_cat + k * TILE + p8;
            ulonglong2 c01 = *(const ulonglong2*)(row);
            ulonglong2 c23 = *(const ulonglong2*)(row + 4);
            u64 w0 = pk2(wv.x), w1 = pk2(wv.y), w2 = pk2(wv.z), w3 = pk2(wv.w);
            A[0] = f2fma(w0, c01.x, A[0]); A[1] = f2fma(w0, c01.y, A[1]);
            A[2] = f2fma(w1, c01.x, A[2]); A[3] = f2fma(w1, c01.y, A[3]);
            A[4] = f2fma(w2, c01.x, A[4]); A[5] = f2fma(w2, c01.y, A[5]);
            A[6] = f2fma(w3, c01.x, A[6]); A[7] = f2fma(w3, c01.y, A[7]);
            B4[0] = f2fma(w0, c23.x, B4[0]); B4[1] = f2fma(w0, c23.y, B4[1]);
            B4[2] = f2fma(w1, c23.x, B4[2]); B4[3] = f2fma(w1, c23.y, B4[3]);
            B4[4] = f2fma(w2, c23.x, B4[4]); B4[5] = f2fma(w2, c23.y, B4[5]);
            B4[6] = f2fma(w3, c23.x, B4[6]); B4[7] = f2fma(w3, c23.y, B4[7]);
        }
        #pragma unroll
        for (int i = 0; i < 4; i++) {
            int oc = oc0 + i;
            float sc = s_sc2[oc], sh = s_sh2[oc];
            float2 q0 = upk(A[2 * i]), q1 = upk(A[2 * i + 1]);
            float2 q2 = upk(B4[2 * i]), q3 = upk(B4[2 * i + 1]);
            float4 o0, o1;
            o0.x = fmaxf(q0.x * sc + sh, 0.f);
            o0.y = fmaxf(q0.y * sc + sh, 0.f);
            o0.z = fmaxf(q1.x * sc + sh, 0.f);
            o0.w = fmaxf(q1.y * sc + sh, 0.f);
            o1.x = fmaxf(q2.x * sc + sh, 0.f);
            o1.y = fmaxf(q2.y * sc + sh, 0.f);
            o1.z = fmaxf(q3.x * sc + sh, 0.f);
            o1.w = fmaxf(q3.y * sc + sh, 0.f);
            float* dst = out + ((size_t)b * OC + oc) * Npts + n0 + p8;
            *(float4*)(dst)     = o0;
            *(float4*)(dst + 4) = o1;
        }
    }
}

extern "C" void kernel_launch(void* const* d_in, const int* in_sizes, int n_in,
                              void* d_out, int out_size) {
    (void)in_sizes; (void)n_in; (void)out_size;
    const float* img_map = (const float*)d_in[0];
    const float* xy      = (const float*)d_in[1];
    const float* pf      = (const float*)d_in[2];
    const float* W_ia    = (const float*)d_in[3];
    const float* b_ia    = (const float*)d_in[4];
    const float* g1      = (const float*)d_in[5];
    const float* bt1     = (const float*)d_in[6];
    const float* m1      = (const float*)d_in[7];
    const float* v1      = (const float*)d_in[8];
    const float* Wf1     = (const float*)d_in[9];
    const float* bf1     = (const float*)d_in[10];
    const float* Wf2     = (const float*)d_in[11];
    const float* bf2     = (const float*)d_in[12];
    const float* Wf3     = (const float*)d_in[13];
    const float* bf3     = (const float*)d_in[14];
    const float* W_fuse  = (const float*)d_in[15];
    const float* b_fuse  = (const float*)d_in[16];
    const float* g2      = (const float*)d_in[17];
    const float* bt2     = (const float*)d_in[18];
    const float* m2      = (const float*)d_in[19];
    const float* v2      = (const float*)d_in[20];
    float* out = (float*)d_out;

    prep_kernel<<<(2 * PC * OC + 255) / 256, 256>>>(
        W_ia, b_ia, g1, bt1, m1, v1, bf1, bf2, Wf3, bf3,
        W_fuse, b_fuse, g2, bt2, m2, v2);

    cudaFuncSetAttribute(fused_rcnn_kernel,
                         cudaFuncAttributeMaxDynamicSharedMemorySize, SMEM_BYTES);
    fused_rcnn_kernel<<<GRID, THREADS, SMEM_BYTES>>>(img_map, xy, pf, Wf1, Wf2, out);
}